// round 8
// baseline (speedup 1.0000x reference)
#include <cuda_runtime.h>
#include <cuda_bf16.h>
#include <math.h>
#include <stdint.h>

// Problem constants
#define BB   64
#define MM   2048
#define DD   256
#define KK   64
#define HH   512
#define XROW 257          // x row = 256 feats + 1 label
#define OUTD 512
#define INVM (1.0f/2048.0f)

// ---------------- scratch (device globals; no allocation) ----------------
__device__ float d_gpart[BB][16][HH];   // stage1 partials per row-tile
__device__ float d_lpart[BB][16];       // label-sum partials
__device__ float d_Lsum[BB];
__device__ float d_logits[BB][MM];      // logits + gumbel
__device__ float d_msg[BB][HH];
__device__ int   d_selIdx[BB][KK];
__device__ float d_selLab[BB];
__device__ float d_g2[BB][HH];

// x features as bf16 hi/lo in MMA A-fragment layout:
// [b][rt][kc][ks][mtile 0..7][lane 0..31][reg 0..3]  (uint32 regs, 16B/lane)
#define XFRAG_N (BB*16*8*2*8*32)        // uint4 count = 4,194,304 (64MB each)
__device__ uint4 d_xhi4[XFRAG_N];
__device__ uint4 d_xlo4[XFRAG_N];
// k1_w0 in MMA B-fragment layout: [kc 8][ks 2][nt 64][lane 32] x {hi0,hi1,lo0,lo1}
#define WFRAG_N (8*2*64*32)             // 32768 uint4 = 512KB
__device__ uint4 d_w0f4[WFRAG_N];

// ---------------- mma.sync helper ----------------
#define MMA16816R(C, A0,A1,A2,A3, B0v, B1v) \
  asm volatile("mma.sync.aligned.m16n8k16.row.col.f32.bf16.bf16.f32 " \
    "{%0,%1,%2,%3}, {%4,%5,%6,%7}, {%8,%9}, {%0,%1,%2,%3};" \
    : "+f"((C)[0]), "+f"((C)[1]), "+f"((C)[2]), "+f"((C)[3]) \
    : "r"(A0), "r"(A1), "r"(A2), "r"(A3), "r"(B0v), "r"(B1v))

__device__ __forceinline__ uint32_t pack_bf16x2(float v0, float v1,
                                                float* r0, float* r1){
    __nv_bfloat16 h0 = __float2bfloat16(v0);
    __nv_bfloat16 h1 = __float2bfloat16(v1);
    *r0 = v0 - __bfloat162float(h0);
    *r1 = v1 - __bfloat162float(h1);
    return (uint32_t)__bfloat16_as_ushort(h0) |
           ((uint32_t)__bfloat16_as_ushort(h1) << 16);
}

// ============================================================================
// prep_x: convert x features to bf16 hi/lo fragments.
// Grid (kc=8, rt=16, b=64), 256 threads. Coalesced smem-staged transpose.
// A-fragment mapping (m16n8k16 row-major A, matches ldmatrix x4 reg order):
//   lane g=lane>>2, t=lane&3; reg0:(r=g,     c=t*2)  reg1:(r=g+8, c=t*2)
//                             reg2:(r=g,     c=t*2+8) reg3:(r=g+8, c=t*2+8)
// ============================================================================
__global__ void __launch_bounds__(256) prep_x_kernel(const float* __restrict__ x)
{
    const int kc = blockIdx.x, rt = blockIdx.y, b = blockIdx.z;
    const int tid = threadIdx.x;
    __shared__ float fs[128][33];

    const float* __restrict__ xb = x + (size_t)(b*MM + rt*128)*XROW;
    #pragma unroll
    for (int it = 0; it < 16; it++){
        int idx = tid + it*256;           // 4096 = 128 rows x 32 k
        int row = idx >> 5, k = idx & 31;
        fs[row][k] = xb[(size_t)row*XROW + kc*32 + k];
    }
    __syncthreads();

    uint32_t* outH = reinterpret_cast<uint32_t*>(d_xhi4);
    uint32_t* outL = reinterpret_cast<uint32_t*>(d_xlo4);
    const size_t gbase = ((size_t)((b*16 + rt)*8 + kc))*2048;   // uint32 units

    #pragma unroll
    for (int it = 0; it < 8; it++){
        int gid  = tid + it*256;          // 0..2047
        int reg  = gid & 3;
        int lane = (gid >> 2) & 31;
        int mt   = (gid >> 7) & 7;
        int ks   = gid >> 10;
        int r = (lane >> 2) + (reg & 1)*8 + mt*16;
        int c = (lane & 3)*2 + (reg >> 1)*8 + ks*16;
        float r0, r1;
        uint32_t hi = pack_bf16x2(fs[r][c], fs[r][c+1], &r0, &r1);
        __nv_bfloat16 l0 = __float2bfloat16(r0);
        __nv_bfloat16 l1 = __float2bfloat16(r1);
        uint32_t lo = (uint32_t)__bfloat16_as_ushort(l0) |
                      ((uint32_t)__bfloat16_as_ushort(l1) << 16);
        outH[gbase + gid] = hi;
        outL[gbase + gid] = lo;
    }
}

// ============================================================================
// prep_w0: k1_w0 (fp32 [k=256][n=512]) -> B-fragment layout.
// B frag (col-major): lane g=lane>>2 (n), t=lane&3:
//   reg0 = {B[k=t*2][n], B[k=t*2+1][n]}   reg1 = {B[k=t*2+8][n], B[k=t*2+9][n]}
// Packed uint4 = {hi0, hi1, lo0, lo1}.
// ============================================================================
__global__ void __launch_bounds__(512) prep_w0_kernel(const float* __restrict__ w0)
{
    int gid = blockIdx.x*512 + threadIdx.x;   // 0..32767
    int lane = gid & 31;
    int nt   = (gid >> 5) & 63;
    int ks   = (gid >> 11) & 1;
    int kc   = gid >> 12;
    int n  = nt*8 + (lane >> 2);
    int kb = kc*32 + ks*16 + (lane & 3)*2;

    float r00, r01, r10, r11;
    uint32_t hi0 = pack_bf16x2(w0[(size_t)kb*HH + n],     w0[(size_t)(kb+1)*HH + n], &r00, &r01);
    uint32_t hi1 = pack_bf16x2(w0[(size_t)(kb+8)*HH + n], w0[(size_t)(kb+9)*HH + n], &r10, &r11);
    uint32_t lo0 = (uint32_t)__bfloat16_as_ushort(__float2bfloat16(r00)) |
                   ((uint32_t)__bfloat16_as_ushort(__float2bfloat16(r01)) << 16);
    uint32_t lo1 = (uint32_t)__bfloat16_as_ushort(__float2bfloat16(r10)) |
                   ((uint32_t)__bfloat16_as_ushort(__float2bfloat16(r11)) << 16);
    uint4 v; v.x = hi0; v.y = hi1; v.z = lo0; v.w = lo1;
    d_w0f4[gid] = v;
}

// ============================================================================
// Stage 1 v2: pure LDG.128 + mma.sync streaming (no smem operands, no syncs
// in the mainloop). Per CTA: D[128 rows][128 cols], K=256.
// Grid (ct=4, rt=16, b=64), 256 thr, 8 warps (warpRow 2 x warpCol 4),
// warp tile 64x32, fp32 accum, 3-term bf16 split.
// ============================================================================
__global__ void __launch_bounds__(256) stage1_mma_kernel(
    const float* __restrict__ x, const float* __restrict__ b0)
{
    const int ct = blockIdx.x;   // 0..3
    const int rt = blockIdx.y;   // 0..15
    const int b  = blockIdx.z;
    const int tid  = threadIdx.x;
    const int lane = tid & 31, wid = tid >> 5;
    const int warpRow = wid & 1;      // 2 row strips of 64
    const int warpCol = wid >> 1;     // 4 col strips of 32

    __shared__ float lab_s[128];
    __shared__ float red2[2][128];

    const float* __restrict__ xb = x + (size_t)(b*MM + rt*128)*XROW;
    if (tid < 128) lab_s[tid] = xb[(size_t)tid*XROW + DD];

    float acc[4][4][4];               // [mf][nf][c]
    #pragma unroll
    for (int i=0;i<4;i++)
        #pragma unroll
        for (int j=0;j<4;j++)
            #pragma unroll
            for (int c=0;c<4;c++) acc[i][j][c] = 0.f;

    const size_t abase0 = ((size_t)((b*16 + rt)*8))*512;   // uint4: per-kc stride 512
    const int amt = warpRow*4;                             // mtile base for this warp
    const int ntb = ct*16 + warpCol*4;                     // ntile base

    #pragma unroll 1
    for (int kc = 0; kc < 8; kc++){
        #pragma unroll
        for (int ks = 0; ks < 2; ks++){
            const uint4* __restrict__ ap = d_xhi4 + abase0 + (size_t)(kc*2 + ks)*256
                                           + (size_t)amt*32 + lane;
            const uint4* __restrict__ lp = d_xlo4 + (ap - d_xhi4);
            uint4 AH[4], AL[4], BF[4];
            #pragma unroll
            for (int mf = 0; mf < 4; mf++){
                AH[mf] = ap[mf*32];
                AL[mf] = lp[mf*32];
            }
            const uint4* __restrict__ bp = d_w0f4 + (size_t)((kc*2 + ks)*64 + ntb)*32 + lane;
            #pragma unroll
            for (int nf = 0; nf < 4; nf++) BF[nf] = bp[nf*32];

            #pragma unroll
            for (int mf = 0; mf < 4; mf++){
                #pragma unroll
                for (int nf = 0; nf < 4; nf++){
                    MMA16816R(acc[mf][nf], AH[mf].x, AH[mf].y, AH[mf].z, AH[mf].w,
                              BF[nf].x, BF[nf].y);               // hi*hi
                    MMA16816R(acc[mf][nf], AH[mf].x, AH[mf].y, AH[mf].z, AH[mf].w,
                              BF[nf].z, BF[nf].w);               // hi*lo
                    MMA16816R(acc[mf][nf], AL[mf].x, AL[mf].y, AL[mf].z, AL[mf].w,
                              BF[nf].x, BF[nf].y);               // lo*hi
                }
            }
        }
    }

    __syncthreads();   // lab_s ready
    // ---- epilogue: bias + relu + label weight, reduce over 128 rows ----
    {
        const int r0 = warpRow*64 + (lane >> 2);
        float cs[4][2];
        #pragma unroll
        for (int nf = 0; nf < 4; nf++){
            const int colg = ct*128 + warpCol*32 + nf*8 + (lane & 3)*2;
            float bias0 = __ldg(&b0[colg]);
            float bias1 = __ldg(&b0[colg+1]);
            float s0 = 0.f, s1 = 0.f;
            #pragma unroll
            for (int mf = 0; mf < 4; mf++){
                float la = lab_s[r0 + mf*16];
                float lb = lab_s[r0 + mf*16 + 8];
                float v;
                v = acc[mf][nf][0] + bias0; v = v>0.f?v:0.f; s0 += la*v;
                v = acc[mf][nf][1] + bias1; v = v>0.f?v:0.f; s1 += la*v;
                v = acc[mf][nf][2] + bias0; v = v>0.f?v:0.f; s0 += lb*v;
                v = acc[mf][nf][3] + bias1; v = v>0.f?v:0.f; s1 += lb*v;
            }
            cs[nf][0] = s0; cs[nf][1] = s1;
        }
        #pragma unroll
        for (int nf = 0; nf < 4; nf++){
            #pragma unroll
            for (int c = 0; c < 2; c++){
                float v = cs[nf][c];
                v += __shfl_down_sync(0xffffffffu, v, 4);
                v += __shfl_down_sync(0xffffffffu, v, 8);
                v += __shfl_down_sync(0xffffffffu, v, 16);
                cs[nf][c] = v;
            }
        }
        if (lane < 4){
            #pragma unroll
            for (int nf = 0; nf < 4; nf++){
                red2[warpRow][warpCol*32 + nf*8 + lane*2 + 0] = cs[nf][0];
                red2[warpRow][warpCol*32 + nf*8 + lane*2 + 1] = cs[nf][1];
            }
        }
    }
    __syncthreads();
    if (tid < 128)
        d_gpart[b][rt][ct*128 + tid] = red2[0][tid] + red2[1][tid];

    if (ct == 0 && tid == 0){
        float s = 0.f;
        #pragma unroll 8
        for (int i = 0; i < 128; i++) s += lab_s[i];
        d_lpart[b][rt] = s;
    }
}

// ============================================================================
// Stage 2: reduce gpart -> g; xt = (g@k1_w1)/M + b1*Lsum/M; m1 MLP + skip;
// logits_full = xt2 @ l1_w + l1_b; add gumbel to first 2048; store msg.
// ============================================================================
__global__ void __launch_bounds__(512) stage2_kernel(
    const float* __restrict__ k1w1, const float* __restrict__ k1b1,
    const float* __restrict__ m1w0, const float* __restrict__ m1b0,
    const float* __restrict__ m1w1, const float* __restrict__ m1b1,
    const float* __restrict__ l1w,  const float* __restrict__ l1b,
    const float* __restrict__ u)
{
    const int b = blockIdx.x;
    const int j = threadIdx.x;
    __shared__ float s0[HH], s1[HH];
    __shared__ float sL;

    float g = 0.f;
    #pragma unroll
    for (int rt=0;rt<16;rt++) g += d_gpart[b][rt][j];
    s0[j] = g;
    if (j == 0){
        float L = 0.f;
        #pragma unroll
        for (int rt=0;rt<16;rt++) L += d_lpart[b][rt];
        sL = L;
        d_Lsum[b] = L;
    }
    __syncthreads();
    const float Ls = sL;

    float acc = 0.f;
    #pragma unroll 4
    for (int k=0;k<HH;k++) acc += s0[k]*k1w1[k*HH + j];
    float xt = acc*INVM + k1b1[j]*(Ls*INVM);
    __syncthreads();
    s1[j] = xt;
    __syncthreads();

    acc = 0.f;
    #pragma unroll 4
    for (int k=0;k<HH;k++) acc += s1[k]*m1w0[k*HH + j];
    float t = fmaxf(acc + m1b0[j], 0.f);
    __syncthreads();
    s0[j] = t;
    __syncthreads();

    acc = 0.f;
    #pragma unroll 4
    for (int k=0;k<HH;k++) acc += s0[k]*m1w1[k*HH + j];
    float x2 = acc + m1b1[j] + xt;
    __syncthreads();
    s1[j] = x2;
    __syncthreads();

    for (int jj=j; jj<HH+MM; jj+=HH){
        float a2 = 0.f;
        #pragma unroll 4
        for (int k=0;k<HH;k++) a2 += s1[k]*l1w[(size_t)k*(HH+MM) + jj];
        a2 += l1b[jj];
        if (jj < MM){
            float uu = u[(size_t)b*MM + jj];
            a2 += -logf(-logf(uu));          // gumbel
            d_logits[b][jj] = a2;
        } else {
            d_msg[b][jj-MM] = a2;
        }
    }
}

// ============================================================================
// Stage 2b: per-batch top-K (K=64) iterative argmax (ties -> lowest index).
// ============================================================================
__global__ void __launch_bounds__(256) topk_kernel(const float* __restrict__ x)
{
    const int b = blockIdx.x;
    const int tid = threadIdx.x;
    __shared__ float v[MM];
    __shared__ float bv[256];
    __shared__ int   bi[256];

    for (int i=tid;i<MM;i+=256) v[i] = d_logits[b][i];
    __syncthreads();

    for (int sel=0; sel<KK; sel++){
        float best = -3.0e38f; int besti = MM;
        for (int i=tid;i<MM;i+=256){
            float val = v[i];
            if (val > best){ best = val; besti = i; }
        }
        bv[tid] = best; bi[tid] = besti;
        __syncthreads();
        for (int s=128;s>0;s>>=1){
            if (tid < s){
                float o = bv[tid+s]; int oi = bi[tid+s];
                if (o > bv[tid] || (o == bv[tid] && oi < bi[tid])){
                    bv[tid] = o; bi[tid] = oi;
                }
            }
            __syncthreads();
        }
        int w = bi[0];
        if (tid == 0){
            d_selIdx[b][sel] = w;
            v[w] = -3.0e38f;
        }
        __syncthreads();
    }

    float s = 0.f;
    if (tid < KK){
        int r = d_selIdx[b][tid];
        s = x[((size_t)b*MM + r)*XROW + DD];
    }
    bv[tid] = s;
    __syncthreads();
    for (int st=128; st>0; st>>=1){
        if (tid < st) bv[tid] += bv[tid+st];
        __syncthreads();
    }
    if (tid == 0) d_selLab[b] = bv[0];
}

// ============================================================================
// Stage 3: gathered tiled GEMM over the 64 selected rows. Grid (4, 64).
// ============================================================================
__global__ void __launch_bounds__(256) stage3_kernel(
    const float* __restrict__ x, const float* __restrict__ w0,
    const float* __restrict__ b0)
{
    const int ct = blockIdx.x;
    const int b  = blockIdx.y;
    const int tid = threadIdx.x;
    const int tx = tid & 15;
    const int ty = tid >> 4;

    __shared__ float As[2][16][68];
    __shared__ float Bs[2][16][128];
    __shared__ float red[16][128];
    __shared__ int   sidx[KK];
    __shared__ float lab[KK];

    if (tid < KK){
        int r = d_selIdx[b][tid];
        sidx[tid] = r;
        lab[tid] = x[((size_t)b*MM + r)*XROW + DD];
    }
    __syncthreads();

    const float* __restrict__ xb  = x + (size_t)b*MM*XROW;
    const float* __restrict__ w0c = w0 + ct*128;

    float acc[4][8];
    #pragma unroll
    for (int i=0;i<4;i++)
        #pragma unroll
        for (int j=0;j<8;j++) acc[i][j]=0.f;

    #pragma unroll
    for (int t=0;t<4;t++){
        int idx = tid + t*256;
        int row = idx >> 4, kk = idx & 15;
        As[0][kk][row] = xb[(size_t)sidx[row]*XROW + kk];
    }
    #pragma unroll
    for (int t=0;t<2;t++){
        int idx = tid + t*256;
        int kk = idx >> 5, colq = idx & 31;
        float4 v = *reinterpret_cast<const float4*>(&w0c[(size_t)kk*HH + colq*4]);
        *reinterpret_cast<float4*>(&Bs[0][kk][colq*4]) = v;
    }
    __syncthreads();

    int buf = 0;
    for (int k0=0;k0<DD;k0+=16){
        if (k0 + 16 < DD){
            int kn = k0 + 16;
            #pragma unroll
            for (int t=0;t<4;t++){
                int idx = tid + t*256;
                int row = idx >> 4, kk = idx & 15;
                As[buf^1][kk][row] = xb[(size_t)sidx[row]*XROW + kn + kk];
            }
            #pragma unroll
            for (int t=0;t<2;t++){
                int idx = tid + t*256;
                int kk = idx >> 5, colq = idx & 31;
                float4 v = *reinterpret_cast<const float4*>(&w0c[(size_t)(kn+kk)*HH + colq*4]);
                *reinterpret_cast<float4*>(&Bs[buf^1][kk][colq*4]) = v;
            }
        }
        #pragma unroll
        for (int kk=0;kk<16;kk++){
            float a[4], bw[8];
            #pragma unroll
            for (int i=0;i<4;i++) a[i]  = As[buf][kk][ty*4+i];
            #pragma unroll
            for (int j=0;j<8;j++) bw[j] = Bs[buf][kk][tx*8+j];
            #pragma unroll
            for (int i=0;i<4;i++)
                #pragma unroll
                for (int j=0;j<8;j++) acc[i][j] += a[i]*bw[j];
        }
        __syncthreads();
        buf ^= 1;
    }

    float lf[4];
    #pragma unroll
    for (int i=0;i<4;i++) lf[i] = lab[ty*4+i];
    float gf[8];
    #pragma unroll
    for (int j=0;j<8;j++){
        float bias = b0[ct*128 + tx*8 + j];
        float s = 0.f;
        #pragma unroll
        for (int i=0;i<4;i++){
            float v = acc[i][j] + bias;
            v = v > 0.f ? v : 0.f;
            s += lf[i]*v;
        }
        gf[j] = s;
    }
    #pragma unroll
    for (int j=0;j<8;j++) red[ty][tx*8+j] = gf[j];
    __syncthreads();
    if (tid < 128){
        float s = 0.f;
        #pragma unroll
        for (int t=0;t<16;t++) s += red[t][tid];
        d_g2[b][ct*128 + tid] = s;
    }
}

// ============================================================================
// Stage 4: final MLP chain -> out.
// ============================================================================
__global__ void __launch_bounds__(512) stage4_kernel(
    const float* __restrict__ k2w1, const float* __restrict__ k2b0,
    const float* __restrict__ k2b1,
    const float* __restrict__ m2w0, const float* __restrict__ m2b0,
    const float* __restrict__ m2w1, const float* __restrict__ m2b1,
    const float* __restrict__ l2w,  const float* __restrict__ l2b,
    float* __restrict__ out)
{
    const int b = blockIdx.x;
    const int j = threadIdx.x;
    __shared__ float g2s[HH];
    __shared__ float zs[2*HH];
    __shared__ float t1[HH];

    const float Ls = d_Lsum[b];
    const float un = Ls - d_selLab[b];
    g2s[j] = d_g2[b][j] + fmaxf(k2b0[j], 0.f)*un;
    __syncthreads();

    float acc = 0.f;
    #pragma unroll 4
    for (int k=0;k<HH;k++) acc += g2s[k]*k2w1[k*HH + j];
    float xt2 = (acc + k2b1[j]*Ls)*INVM;

    zs[j]      = xt2;
    zs[HH + j] = d_msg[b][j];
    __syncthreads();

    acc = 0.f;
    #pragma unroll 4
    for (int k=0;k<2*HH;k++) acc += zs[k]*m2w0[(size_t)k*HH + j];
    t1[j] = fmaxf(acc + m2b0[j], 0.f);
    __syncthreads();

    float y0 = 0.f, y1 = 0.f;
    #pragma unroll 4
    for (int k=0;k<HH;k++){
        float t = t1[k];
        y0 += t*m2w1[(size_t)k*(2*HH) + j];
        y1 += t*m2w1[(size_t)k*(2*HH) + j + HH];
    }
    y0 = fmaxf(y0 + m2b1[j],      0.f) + zs[j];
    y1 = fmaxf(y1 + m2b1[j + HH], 0.f) + zs[HH + j];
    __syncthreads();
    zs[j]      = y0;
    zs[HH + j] = y1;
    __syncthreads();

    acc = 0.f;
    #pragma unroll 4
    for (int k=0;k<2*HH;k++) acc += zs[k]*l2w[(size_t)k*OUTD + j];
    out[(size_t)b*OUTD + j] = acc + l2b[j];
}

// ============================================================================
extern "C" void kernel_launch(void* const* d_in, const int* in_sizes, int n_in,
                              void* d_out, int out_size)
{
    const float* x     = (const float*)d_in[0];
    const float* u     = (const float*)d_in[1];
    const float* k1w0  = (const float*)d_in[2];
    const float* k1b0  = (const float*)d_in[3];
    const float* k1w1  = (const float*)d_in[4];
    const float* k1b1  = (const float*)d_in[5];
    const float* k2w0  = (const float*)d_in[6];
    const float* k2b0  = (const float*)d_in[7];
    const float* k2w1  = (const float*)d_in[8];
    const float* k2b1  = (const float*)d_in[9];
    const float* m1w0  = (const float*)d_in[10];
    const float* m1b0  = (const float*)d_in[11];
    const float* m1w1  = (const float*)d_in[12];
    const float* m1b1  = (const float*)d_in[13];
    const float* m2w0  = (const float*)d_in[14];
    const float* m2b0  = (const float*)d_in[15];
    const float* m2w1  = (const float*)d_in[16];
    const float* m2b1  = (const float*)d_in[17];
    const float* l1w   = (const float*)d_in[18];
    const float* l1b   = (const float*)d_in[19];
    const float* l2w   = (const float*)d_in[20];
    const float* l2b   = (const float*)d_in[21];
    float* out = (float*)d_out;

    prep_w0_kernel<<<64, 512>>>(k1w0);
    dim3 gpx(8, 16, BB);
    prep_x_kernel<<<gpx, 256>>>(x);
    dim3 g1(4, 16, BB);
    stage1_mma_kernel<<<g1, 256>>>(x, k1b0);
    stage2_kernel<<<BB, 512>>>(k1w1, k1b1, m1w0, m1b0, m1w1, m1b1, l1w, l1b, u);
    topk_kernel<<<BB, 256>>>(x);
    dim3 g3(4, BB);
    stage3_kernel<<<g3, 256>>>(x, k2w0, k2b0);
    stage4_kernel<<<BB, 512>>>(k2w1, k2b0, k2b1, m2w0, m2b0, m2w1, m2b1,
                               l2w, l2b, out);
}